// round 11
// baseline (speedup 1.0000x reference)
#include <cuda_runtime.h>
#include <cuda_bf16.h>
#include <cstdint>

typedef unsigned int u32;
typedef unsigned long long u64;

// Problem constants
constexpr int Bq = 2, Eq = 16, Hq = 160, Wq = 288, Nq = 12, Tq = 2;
constexpr int HW  = Hq * Wq;            // 46080
constexpr int P   = Tq * HW;            // 92160
constexpr int BN  = Bq * Nq;            // 24 instances

constexpr int CPIX = 1280;              // pixels per chunk
constexpr int CH   = HW / CPIX;         // 36 chunks per (b,t)
constexpr int NBLK = Bq * Tq * CH;      // 144 blocks (<= SM count: co-resident)
constexpr int NCHK2 = Tq * CH * 2;      // 144 half-chunk partials per instance
constexpr int HITER = (CPIX / 128) / 2; // 5 iters per half-warp (32 lanes x 4 px)
constexpr int THREADS = 768;            // 24 warps: 2 warps per instance

constexpr int NB  = 1024;               // histogram bins over err in [0,2]
constexpr float FXS = 4096.0f;          // fixed-point 2^12
// hist packing: (pos<<47) | (neg<<30) | fxsum

constexpr int LTH = 256;                // loss scan lanes
constexpr int LIT = NB / LTH;           // 4 bins per lane

// -------- scratch --------
__device__ float g_part[BN * NCHK2 * 33];
__device__ float g_w2[BN * Eq];
__device__ float g_w1[BN * Eq];
__device__ float g_c[BN];
__device__ float g_cnt[BN];
__device__ u64 g_hist[BN * NB];
__device__ float g_losspart[BN];
__device__ int g_sync = 0;              // monotonic grid barrier counter
__device__ int g_done_l = 0;            // loss finalize counter

__device__ __forceinline__ void gridbar(int phase) {
    __syncthreads();
    if (threadIdx.x == 0) {
        __threadfence();
        atomicAdd(&g_sync, 1);
        while (atomicAdd(&g_sync, 0) < phase * NBLK) __nanosleep(64);
    }
    __syncthreads();
}

__global__ void __launch_bounds__(THREADS, 1) k_fused(
    const float* __restrict__ f1, const float* __restrict__ f2,
    const int* __restrict__ gt, float* __restrict__ out) {
    int blk = blockIdx.x;
    int tid = threadIdx.x;
    int b = blk / (Tq * CH);
    int r = blk % (Tq * CH);
    int t = r / CH, ch = r % CH;
    int hw0 = ch * CPIX;
    const float* fb = (t ? f2 : f1) + (size_t)b * Eq * HW + hw0;

    // replay-safe counter reset: no block passes barrier1 until all blocks
    // have started, so CAS(3*NBLK -> 0) never races with a spinning block.
    if (tid == 0) atomicCAS(&g_sync, 3 * NBLK, 0);
    __syncthreads();

    // zero hist slice (completion covered by barrier 1)
    for (int i = blk * THREADS + tid; i < BN * NB; i += NBLK * THREADS)
        g_hist[i] = 0ull;

    int w = tid >> 5, lane = tid & 31;
    int inst = w % Nq;                  // instance for this warp
    int half = w / Nq;                  // 0 or 1: which half of the chunk
    int bn = b * Nq + inst;
    const int4* gt4 = (const int4*)(gt + ((size_t)bn * Tq + t) * HW + hw0);
    int ibase = half * (HITER * 32);    // in float4 units

    // ================= phase 1: stats =================
    {
        float a[33];
#pragma unroll
        for (int q = 0; q < 33; q++) a[q] = 0.f;

#pragma unroll
        for (int it = 0; it < HITER; it++) {
            int i4 = ibase + it * 32 + lane;
            int4 mm = gt4[i4];
            a[32] += (float)(mm.x + mm.y + mm.z + mm.w);
#pragma unroll
            for (int e = 0; e < Eq; e++) {
                float4 v = ((const float4*)(fb + (size_t)e * HW))[i4];
                float x0 = mm.x ? v.x : 0.f;
                float x1 = mm.y ? v.y : 0.f;
                float x2 = mm.z ? v.z : 0.f;
                float x3 = mm.w ? v.w : 0.f;
                a[e] += (x0 + x1) + (x2 + x3);
                a[16 + e] += fmaf(x0, v.x, fmaf(x1, v.y, fmaf(x2, v.z, x3 * v.w)));
            }
        }
#pragma unroll
        for (int q = 0; q < 33; q++)
#pragma unroll
            for (int off = 16; off > 0; off >>= 1)
                a[q] += __shfl_down_sync(0xFFFFFFFFu, a[q], off);

        if (lane == 0) {
            int ci = (t * CH + ch) * 2 + half;
            float* dst = &g_part[((size_t)bn * NCHK2 + ci) * 33];
#pragma unroll
            for (int q = 0; q < 33; q++) dst[q] = a[q];
        }
    }

    gridbar(1);

    // ================= phase 2: finalize (blocks 0..23) =================
    if (blk < BN) {
        __shared__ float fs[33][8];
        __shared__ float sums[33];
        __shared__ float vm2[Eq];
        int ibn = blk;
        if (tid < 264) {
            int q = tid >> 3, sl = tid & 7;   // q 0..32, slice 0..7
            float s = 0.f;
            for (int c = sl * 18; c < sl * 18 + 18; c++)
                s += g_part[((size_t)ibn * NCHK2 + c) * 33 + q];
            fs[q][sl] = s;
        }
        __syncthreads();
        if (tid < 33) {
            float s = 0.f;
#pragma unroll
            for (int sl = 0; sl < 8; sl++) s += fs[tid][sl];
            sums[tid] = s;
        }
        __syncthreads();
        float cnt = sums[32];
        if (tid < Eq) {
            float mean = sums[tid] / cnt;
            float var  = (sums[16 + tid] - cnt * mean * mean) / (cnt - 1.0f);
            g_w2[ibn * Eq + tid] = var;
            g_w1[ibn * Eq + tid] = -2.0f * var * mean;
            vm2[tid] = var * mean * mean;
        }
        __syncthreads();
        if (tid == 0) {
            float c = 0.f;
#pragma unroll
            for (int e = 0; e < Eq; e++) c += vm2[e];
            g_c[ibn] = c;
            g_cnt[ibn] = cnt;
        }
    }

    gridbar(2);

    // ================= phase 3: errhist (L1-warm feat window) =============
    {
        size_t gb = (size_t)bn * NB;
        float w2[Eq], w1[Eq];
#pragma unroll
        for (int e = 0; e < Eq; e++) {
            w2[e] = g_w2[bn * Eq + e];
            w1[e] = g_w1[bn * Eq + e];
        }
        float cc = g_c[bn];

        u32 c0 = 0, cM = 0, s0 = 0, sM = 0;

#pragma unroll
        for (int it = 0; it < HITER; it++) {
            int i4 = ibase + it * 32 + lane;
            int4 mm = gt4[i4];
            float d0 = cc, d1 = cc, d2 = cc, d3 = cc;
#pragma unroll
            for (int e = 0; e < Eq; e++) {
                float4 v = ((const float4*)(fb + (size_t)e * HW))[i4];
                d0 = fmaf(v.x, fmaf(v.x, w2[e], w1[e]), d0);
                d1 = fmaf(v.y, fmaf(v.y, w2[e], w1[e]), d1);
                d2 = fmaf(v.z, fmaf(v.z, w2[e], w1[e]), d2);
                d3 = fmaf(v.w, fmaf(v.w, w2[e], w1[e]), d3);
            }
            float dd[4] = {d0, d1, d2, d3};
            int msk[4] = {mm.x, mm.y, mm.z, mm.w};
#pragma unroll
            for (int j = 0; j < 4; j++) {
                float logit = 2.0f * __expf(-0.5f * dd[j]) - 1.0f;
                float err = msk[j] ? (1.0f - logit) : (1.0f + logit);
                u32 fx = (u32)(err * FXS + 0.5f);
                int bin = (int)(err * (0.5f * NB));
                if (bin > NB - 1) bin = NB - 1;
                u32 pc = msk[j] ? 0x10000u : 1u;
                if (bin == 0)           { c0 += pc; s0 += fx; }
                else if (bin == NB - 1) { cM += pc; sM += fx; }
                else {
                    u64 add = (msk[j] ? (1ull << 47) : (1ull << 30)) | (u64)fx;
                    atomicAdd(&g_hist[gb + bin], add);
                }
            }
        }
#pragma unroll
        for (int off = 16; off > 0; off >>= 1) {
            c0 += __shfl_down_sync(0xFFFFFFFFu, c0, off);
            cM += __shfl_down_sync(0xFFFFFFFFu, cM, off);
            s0 += __shfl_down_sync(0xFFFFFFFFu, s0, off);
            sM += __shfl_down_sync(0xFFFFFFFFu, sM, off);
        }
        if (lane == 0) {
            if (c0)
                atomicAdd(&g_hist[gb + 0],
                    ((u64)(c0 >> 16) << 47) | ((u64)(c0 & 0xFFFFu) << 30) | (u64)s0);
            if (cM)
                atomicAdd(&g_hist[gb + NB - 1],
                    ((u64)(cM >> 16) << 47) | ((u64)(cM & 0xFFFFu) << 30) | (u64)sM);
        }
    }

    gridbar(3);

    // ================= phase 4: Lovász scan (blocks 0..23) ================
    if (blk >= BN) return;
    {
        int ibn = blk;
        float gts = g_cnt[ibn];
        size_t gbase = (size_t)ibn * NB;

        u32 pos[LIT], tot[LIT], fx[LIT];
        u64 tsum = 0ull;
        if (tid < LTH) {
#pragma unroll
            for (int i = 0; i < LIT; i++) {
                int bin = NB - 1 - (tid * LIT + i);
                u64 h = g_hist[gbase + bin];
                pos[i] = (u32)(h >> 47);
                u32 neg = (u32)(h >> 30) & 0x1FFFFu;
                tot[i] = pos[i] + neg;
                fx[i]  = (u32)(h & 0x3FFFFFFFull);
                tsum += ((u64)pos[i] << 32) | (u64)tot[i];
            }
        }

        // hand-rolled exclusive scan over 256 lanes (8 warps)
        __shared__ u64 wtot[8];
        u64 inc = tsum;
        if (tid < LTH) {
#pragma unroll
            for (int off = 1; off < 32; off <<= 1) {
                u64 n = __shfl_up_sync(0xFFFFFFFFu, inc, off);
                if (lane >= off) inc += n;
            }
            if (lane == 31) wtot[w] = inc;
        }
        __syncthreads();
        float loss = 0.f;
        if (tid < LTH) {
            u64 wpref = 0ull;
            for (int ww = 0; ww < w; ww++) wpref += wtot[ww];
            u64 run = wpref + inc - tsum;    // exclusive prefix
#pragma unroll
            for (int i = 0; i < LIT; i++) {
                if (tot[i]) {
                    float cA = (float)(u32)(run >> 32);
                    float kA = (float)(u32)(run & 0xFFFFFFFFull);
                    float cB = cA + (float)pos[i];
                    float kB = kA + (float)tot[i];
                    float JA = 1.0f - (gts - cA) / (gts + kA - cA);
                    float JB = 1.0f - (gts - cB) / (gts + kB - cB);
                    float err_rep = (float)fx[i] / (FXS * (float)tot[i]);
                    loss += err_rep * (JB - JA);
                }
                run += ((u64)pos[i] << 32) | (u64)tot[i];
            }
        }

        __shared__ float red[LTH];
        if (tid < LTH) red[tid] = loss;
        __syncthreads();
        for (int s = LTH / 2; s > 0; s >>= 1) {
            if (tid < s) red[tid] += red[tid + s];
            __syncthreads();
        }

        __shared__ bool is_last;
        if (tid == 0) {
            g_losspart[ibn] = red[0];
            __threadfence();
            int done = atomicAdd(&g_done_l, 1);
            is_last = (done == BN - 1);
        }
        __syncthreads();
        if (is_last && tid == 0) {
            __threadfence();
            float s = 0.f;
#pragma unroll
            for (int i = 0; i < BN; i++) s += g_losspart[i];
            out[0] = s / (float)BN;
            g_done_l = 0;               // reset for next replay
        }
    }
}

extern "C" void kernel_launch(void* const* d_in, const int* in_sizes, int n_in,
                              void* d_out, int out_size) {
    const float* f1 = (const float*)d_in[0];
    const float* f2 = (const float*)d_in[1];
    const int*   gt = (const int*)d_in[2];
    float* out = (float*)d_out;
    k_fused<<<NBLK, THREADS>>>(f1, f2, gt, out);
}

// round 12
// speedup vs baseline: 3.0235x; 3.0235x over previous
#include <cuda_runtime.h>
#include <cuda_bf16.h>
#include <cstdint>

typedef unsigned int u32;
typedef unsigned long long u64;

// Problem constants
constexpr int Bq = 2, Eq = 16, Hq = 160, Wq = 288, Nq = 12, Tq = 2;
constexpr int HW  = Hq * Wq;            // 46080
constexpr int P   = Tq * HW;            // 92160
constexpr int BN  = Bq * Nq;            // 24 instances

constexpr int CPIX = 1280;              // pixels per chunk
constexpr int CH   = HW / CPIX;         // 36 chunks per (b,t)
constexpr int NBLK = Bq * Tq * CH;      // 144 blocks (<= SM count: co-resident)
constexpr int NCHK = Tq * CH;           // 72 partial chunks per instance
constexpr int ITER4 = CPIX / 128;       // 10 iters (32 lanes x 4 px)
constexpr int THREADS = 384;
constexpr int C4 = CPIX / 4;            // 320 float4 per plane

constexpr int NB  = 1024;               // histogram bins over err in [0,2]
constexpr float FXS = 4096.0f;          // fixed-point 2^12
// hist packing: (pos<<47) | (neg<<30) | fxsum

constexpr int LTH = 256;                // loss scan lanes
constexpr int LIT = NB / LTH;           // 4 bins per lane

// dynamic smem: float tile[Eq*CPIX] (80KB) + u32 msk[Nq*ITER4*4] (1.92KB)
constexpr int SMEM_DYN = Eq * CPIX * 4 + Nq * ITER4 * 4 * 4;

// -------- scratch --------
__device__ float g_part[BN * NCHK * 33];
__device__ float g_w2[BN * Eq];
__device__ float g_w1[BN * Eq];
__device__ float g_c[BN];
__device__ float g_cnt[BN];
__device__ u64 g_hist[BN * NB];
__device__ float g_losspart[BN];
__device__ int g_sync = 0;              // monotonic grid barrier counter
__device__ int g_done_l = 0;            // loss finalize counter

__device__ __forceinline__ void gridbar(int phase) {
    __syncthreads();
    if (threadIdx.x == 0) {
        __threadfence();
        atomicAdd(&g_sync, 1);
        while (atomicAdd(&g_sync, 0) < phase * NBLK) __nanosleep(64);
    }
    __syncthreads();
}

__global__ void __launch_bounds__(THREADS, 1) k_fused(
    const float* __restrict__ f1, const float* __restrict__ f2,
    const int* __restrict__ gt, float* __restrict__ out) {
    extern __shared__ u32 smem_raw[];
    float* tile = (float*)smem_raw;                 // [Eq][CPIX]
    u32* msk = smem_raw + Eq * CPIX;                // [Nq][ITER4*4]

    int blk = blockIdx.x;
    int tid = threadIdx.x;
    int b = blk / (Tq * CH);
    int r = blk % (Tq * CH);
    int t = r / CH, ch = r % CH;
    int hw0 = ch * CPIX;
    const float* fb = (t ? f2 : f1) + (size_t)b * Eq * HW + hw0;

    // replay-safe counter reset: no block passes barrier1 until all blocks
    // have started, so CAS(3*NBLK -> 0) never races with a spinning block.
    if (tid == 0) atomicCAS(&g_sync, 3 * NBLK, 0);

    // cooperative feat tile load (coalesced float4)
    for (int idx = tid; idx < Eq * C4; idx += THREADS) {
        int e = idx / C4, i = idx - e * C4;
        ((float4*)(tile + e * CPIX))[i] = ((const float4*)(fb + (size_t)e * HW))[i];
    }

    // zero hist slice (completion covered by barrier 1)
    for (int i = blk * THREADS + tid; i < BN * NB; i += NBLK * THREADS)
        g_hist[i] = 0ull;
    __syncthreads();

    int w = tid >> 5, lane = tid & 31;  // warp w = instance w
    int bn = b * Nq + w;
    const int4* gt4 = (const int4*)(gt + ((size_t)bn * Tq + t) * HW + hw0);

    // ================= phase 1: stats (+ cache gt ballots) =================
    {
        float a[33];
#pragma unroll
        for (int q = 0; q < 33; q++) a[q] = 0.f;

        for (int it = 0; it < ITER4; it++) {
            int i4 = it * 32 + lane;
            int4 mm = gt4[i4];
            // cache masks as ballots for phase 3
            u32 b0 = __ballot_sync(0xFFFFFFFFu, mm.x);
            u32 b1 = __ballot_sync(0xFFFFFFFFu, mm.y);
            u32 b2 = __ballot_sync(0xFFFFFFFFu, mm.z);
            u32 b3 = __ballot_sync(0xFFFFFFFFu, mm.w);
            if (lane == 0) {
                msk[w * (ITER4 * 4) + it * 4 + 0] = b0;
                msk[w * (ITER4 * 4) + it * 4 + 1] = b1;
                msk[w * (ITER4 * 4) + it * 4 + 2] = b2;
                msk[w * (ITER4 * 4) + it * 4 + 3] = b3;
            }
            a[32] += (float)(mm.x + mm.y + mm.z + mm.w);
#pragma unroll
            for (int e = 0; e < Eq; e++) {
                float4 v = ((const float4*)(tile + e * CPIX))[i4];
                float x0 = mm.x ? v.x : 0.f;
                float x1 = mm.y ? v.y : 0.f;
                float x2 = mm.z ? v.z : 0.f;
                float x3 = mm.w ? v.w : 0.f;
                a[e] += (x0 + x1) + (x2 + x3);
                a[16 + e] += fmaf(x0, v.x, fmaf(x1, v.y, fmaf(x2, v.z, x3 * v.w)));
            }
        }
#pragma unroll
        for (int q = 0; q < 33; q++)
#pragma unroll
            for (int off = 16; off > 0; off >>= 1)
                a[q] += __shfl_down_sync(0xFFFFFFFFu, a[q], off);

        if (lane == 0) {
            float* dst = &g_part[((size_t)bn * NCHK + (t * CH + ch)) * 33];
#pragma unroll
            for (int q = 0; q < 33; q++) dst[q] = a[q];
        }
    }

    gridbar(1);

    // ================= phase 2: finalize (blocks 0..23) =================
    if (blk < BN) {
        __shared__ float fs[33][8];
        __shared__ float sums[33];
        __shared__ float vm2[Eq];
        int ibn = blk;
        if (tid < 264) {
            int q = tid >> 3, sl = tid & 7;   // q 0..32, slice 0..7
            float s = 0.f;
            for (int c = sl * 9; c < sl * 9 + 9; c++)
                s += g_part[((size_t)ibn * NCHK + c) * 33 + q];
            fs[q][sl] = s;
        }
        __syncthreads();
        if (tid < 33) {
            float s = 0.f;
#pragma unroll
            for (int sl = 0; sl < 8; sl++) s += fs[tid][sl];
            sums[tid] = s;
        }
        __syncthreads();
        float cnt = sums[32];
        if (tid < Eq) {
            float mean = sums[tid] / cnt;
            float var  = (sums[16 + tid] - cnt * mean * mean) / (cnt - 1.0f);
            g_w2[ibn * Eq + tid] = var;
            g_w1[ibn * Eq + tid] = -2.0f * var * mean;
            vm2[tid] = var * mean * mean;
        }
        __syncthreads();
        if (tid == 0) {
            float c = 0.f;
#pragma unroll
            for (int e = 0; e < Eq; e++) c += vm2[e];
            g_c[ibn] = c;
            g_cnt[ibn] = cnt;
        }
    }

    gridbar(2);

    // ================= phase 3: errhist (all from smem) =============
    {
        size_t gb = (size_t)bn * NB;
        float w2[Eq], w1[Eq];
#pragma unroll
        for (int e = 0; e < Eq; e++) {
            w2[e] = g_w2[bn * Eq + e];
            w1[e] = g_w1[bn * Eq + e];
        }
        float cc = g_c[bn];

        u32 c0 = 0, cM = 0, s0 = 0, sM = 0;

        for (int it = 0; it < ITER4; it++) {
            int i4 = it * 32 + lane;
            u32 mb0 = msk[w * (ITER4 * 4) + it * 4 + 0];
            u32 mb1 = msk[w * (ITER4 * 4) + it * 4 + 1];
            u32 mb2 = msk[w * (ITER4 * 4) + it * 4 + 2];
            u32 mb3 = msk[w * (ITER4 * 4) + it * 4 + 3];
            int msk4[4] = { (int)((mb0 >> lane) & 1u), (int)((mb1 >> lane) & 1u),
                            (int)((mb2 >> lane) & 1u), (int)((mb3 >> lane) & 1u) };
            float d0 = cc, d1 = cc, d2 = cc, d3 = cc;
#pragma unroll
            for (int e = 0; e < Eq; e++) {
                float4 v = ((const float4*)(tile + e * CPIX))[i4];
                d0 = fmaf(v.x, fmaf(v.x, w2[e], w1[e]), d0);
                d1 = fmaf(v.y, fmaf(v.y, w2[e], w1[e]), d1);
                d2 = fmaf(v.z, fmaf(v.z, w2[e], w1[e]), d2);
                d3 = fmaf(v.w, fmaf(v.w, w2[e], w1[e]), d3);
            }
            float dd[4] = {d0, d1, d2, d3};
#pragma unroll
            for (int j = 0; j < 4; j++) {
                float logit = 2.0f * __expf(-0.5f * dd[j]) - 1.0f;
                float err = msk4[j] ? (1.0f - logit) : (1.0f + logit);
                u32 fx = (u32)(err * FXS + 0.5f);
                int bin = (int)(err * (0.5f * NB));
                if (bin > NB - 1) bin = NB - 1;
                u32 pc = msk4[j] ? 0x10000u : 1u;
                if (bin == 0)           { c0 += pc; s0 += fx; }
                else if (bin == NB - 1) { cM += pc; sM += fx; }
                else {
                    u64 add = (msk4[j] ? (1ull << 47) : (1ull << 30)) | (u64)fx;
                    atomicAdd(&g_hist[gb + bin], add);
                }
            }
        }
#pragma unroll
        for (int off = 16; off > 0; off >>= 1) {
            c0 += __shfl_down_sync(0xFFFFFFFFu, c0, off);
            cM += __shfl_down_sync(0xFFFFFFFFu, cM, off);
            s0 += __shfl_down_sync(0xFFFFFFFFu, s0, off);
            sM += __shfl_down_sync(0xFFFFFFFFu, sM, off);
        }
        if (lane == 0) {
            if (c0)
                atomicAdd(&g_hist[gb + 0],
                    ((u64)(c0 >> 16) << 47) | ((u64)(c0 & 0xFFFFu) << 30) | (u64)s0);
            if (cM)
                atomicAdd(&g_hist[gb + NB - 1],
                    ((u64)(cM >> 16) << 47) | ((u64)(cM & 0xFFFFu) << 30) | (u64)sM);
        }
    }

    gridbar(3);

    // ================= phase 4: Lovász scan (blocks 0..23) ================
    if (blk >= BN) return;
    {
        int ibn = blk;
        float gts = g_cnt[ibn];
        size_t gbase = (size_t)ibn * NB;

        u32 pos[LIT], tot[LIT], fx[LIT];
        u64 tsum = 0ull;
        if (tid < LTH) {
#pragma unroll
            for (int i = 0; i < LIT; i++) {
                int bin = NB - 1 - (tid * LIT + i);
                u64 h = g_hist[gbase + bin];
                pos[i] = (u32)(h >> 47);
                u32 neg = (u32)(h >> 30) & 0x1FFFFu;
                tot[i] = pos[i] + neg;
                fx[i]  = (u32)(h & 0x3FFFFFFFull);
                tsum += ((u64)pos[i] << 32) | (u64)tot[i];
            }
        }

        // hand-rolled exclusive scan over 256 lanes (8 warps)
        __shared__ u64 wtot[8];
        u64 inc = tsum;
        if (tid < LTH) {
#pragma unroll
            for (int off = 1; off < 32; off <<= 1) {
                u64 n = __shfl_up_sync(0xFFFFFFFFu, inc, off);
                if (lane >= off) inc += n;
            }
            if (lane == 31) wtot[w] = inc;
        }
        __syncthreads();
        float loss = 0.f;
        if (tid < LTH) {
            u64 wpref = 0ull;
            for (int ww = 0; ww < w; ww++) wpref += wtot[ww];
            u64 run = wpref + inc - tsum;    // exclusive prefix
#pragma unroll
            for (int i = 0; i < LIT; i++) {
                if (tot[i]) {
                    float cA = (float)(u32)(run >> 32);
                    float kA = (float)(u32)(run & 0xFFFFFFFFull);
                    float cB = cA + (float)pos[i];
                    float kB = kA + (float)tot[i];
                    float JA = 1.0f - (gts - cA) / (gts + kA - cA);
                    float JB = 1.0f - (gts - cB) / (gts + kB - cB);
                    float err_rep = (float)fx[i] / (FXS * (float)tot[i]);
                    loss += err_rep * (JB - JA);
                }
                run += ((u64)pos[i] << 32) | (u64)tot[i];
            }
        }

        __shared__ float red[LTH];
        if (tid < LTH) red[tid] = loss;
        __syncthreads();
        for (int s = LTH / 2; s > 0; s >>= 1) {
            if (tid < s) red[tid] += red[tid + s];
            __syncthreads();
        }

        __shared__ bool is_last;
        if (tid == 0) {
            g_losspart[ibn] = red[0];
            __threadfence();
            int done = atomicAdd(&g_done_l, 1);
            is_last = (done == BN - 1);
        }
        __syncthreads();
        if (is_last && tid == 0) {
            __threadfence();
            float s = 0.f;
#pragma unroll
            for (int i = 0; i < BN; i++) s += g_losspart[i];
            out[0] = s / (float)BN;
            g_done_l = 0;               // reset for next replay
        }
    }
}

extern "C" void kernel_launch(void* const* d_in, const int* in_sizes, int n_in,
                              void* d_out, int out_size) {
    const float* f1 = (const float*)d_in[0];
    const float* f2 = (const float*)d_in[1];
    const int*   gt = (const int*)d_in[2];
    float* out = (float*)d_out;
    cudaFuncSetAttribute(k_fused, cudaFuncAttributeMaxDynamicSharedMemorySize,
                         SMEM_DYN);
    k_fused<<<NBLK, THREADS, SMEM_DYN>>>(f1, f2, gt, out);
}

// round 14
// speedup vs baseline: 3.2100x; 1.0617x over previous
#include <cuda_runtime.h>
#include <cuda_bf16.h>
#include <cstdint>

typedef unsigned int u32;
typedef unsigned long long u64;

// Problem constants
constexpr int Bq = 2, Eq = 16, Hq = 160, Wq = 288, Nq = 12, Tq = 2;
constexpr int HW  = Hq * Wq;            // 46080
constexpr int P   = Tq * HW;            // 92160
constexpr int BN  = Bq * Nq;            // 24 instances

constexpr int CPIX = 1280;              // pixels per chunk (tile)
constexpr int CH   = HW / CPIX;         // 36 chunks per (b,t)
constexpr int NBLK = Bq * Tq * CH;      // 144 blocks (co-resident, 1/SM)
constexpr int NCHK2 = Tq * CH * 2;      // 144 half-chunk partials per instance
constexpr int HITER = 5;                // float4-iters per half-warp (5*32*4 = 640 px)
constexpr int THREADS = 768;            // 24 warps: (instance, half)
constexpr int C4 = CPIX / 4;            // 320 float4 per plane

constexpr int NB  = 1024;               // histogram bins over err in [0,2]
constexpr float FXS = 4096.0f;          // fixed-point 2^12
// hist packing: (pos<<47) | (neg<<30) | fxsum

constexpr int LTH = 256;                // loss scan lanes
constexpr int LIT = NB / LTH;           // 4 bins per lane

// dynamic smem: float tile[Eq*CPIX] (80KB) + u32 msk[24][HITER*4] (1.92KB)
constexpr int SMEM_DYN = Eq * CPIX * 4 + 24 * HITER * 4 * 4;

// -------- scratch --------
__device__ float g_part[BN * NCHK2 * 33];
__device__ float g_w2[BN * Eq];
__device__ float g_w1[BN * Eq];
__device__ float g_c[BN];
__device__ float g_cnt[BN];
__device__ u64 g_hist[BN * NB];
__device__ float g_losspart[BN];
__device__ int g_sync = 0;              // monotonic grid barrier counter
__device__ int g_done_l = 0;            // loss finalize counter

__device__ __forceinline__ void gridbar(int phase) {
    __syncthreads();
    if (threadIdx.x == 0) {
        __threadfence();
        atomicAdd(&g_sync, 1);
        while (atomicAdd(&g_sync, 0) < phase * NBLK) __nanosleep(64);
    }
    __syncthreads();
}

__global__ void __launch_bounds__(THREADS, 1) k_fused(
    const float* __restrict__ f1, const float* __restrict__ f2,
    const int* __restrict__ gt, float* __restrict__ out) {
    extern __shared__ u32 smem_raw[];
    float* tile = (float*)smem_raw;                 // [Eq][CPIX]
    u32* msk = smem_raw + Eq * CPIX;                // [24][HITER*4]

    int blk = blockIdx.x;
    int tid = threadIdx.x;
    int b = blk / (Tq * CH);
    int r = blk % (Tq * CH);
    int t = r / CH, ch = r % CH;
    int hw0 = ch * CPIX;
    const float* fb = (t ? f2 : f1) + (size_t)b * Eq * HW + hw0;

    // replay-safe counter reset: no block passes barrier1 until all blocks
    // have started, so CAS(3*NBLK -> 0) never races with a spinning block.
    if (tid == 0) atomicCAS(&g_sync, 3 * NBLK, 0);

    // cooperative feat tile load (coalesced float4)
    for (int idx = tid; idx < Eq * C4; idx += THREADS) {
        int e = idx / C4, i = idx - e * C4;
        ((float4*)(tile + e * CPIX))[i] = ((const float4*)(fb + (size_t)e * HW))[i];
    }

    // zero hist slice (completion covered by barrier 1)
    for (int i = blk * THREADS + tid; i < BN * NB; i += NBLK * THREADS)
        g_hist[i] = 0ull;
    __syncthreads();

    int w = tid >> 5, lane = tid & 31;
    int inst = w % Nq;                  // instance
    int half = w / Nq;                  // 0/1: pixel half of the tile
    int bn = b * Nq + inst;
    const int4* gt4 = (const int4*)(gt + ((size_t)bn * Tq + t) * HW + hw0);
    int ibase = half * (HITER * 32);    // float4 units

    // ================= phase 1: stats (+ cache gt ballots) =================
    {
        float a[33];
#pragma unroll
        for (int q = 0; q < 33; q++) a[q] = 0.f;

#pragma unroll
        for (int it = 0; it < HITER; it++) {
            int i4 = ibase + it * 32 + lane;
            int4 mm = gt4[i4];
            u32 b0 = __ballot_sync(0xFFFFFFFFu, mm.x);
            u32 b1 = __ballot_sync(0xFFFFFFFFu, mm.y);
            u32 b2 = __ballot_sync(0xFFFFFFFFu, mm.z);
            u32 b3 = __ballot_sync(0xFFFFFFFFu, mm.w);
            if (lane == 0) {
                msk[w * (HITER * 4) + it * 4 + 0] = b0;
                msk[w * (HITER * 4) + it * 4 + 1] = b1;
                msk[w * (HITER * 4) + it * 4 + 2] = b2;
                msk[w * (HITER * 4) + it * 4 + 3] = b3;
            }
            a[32] += (float)(mm.x + mm.y + mm.z + mm.w);
#pragma unroll
            for (int e = 0; e < Eq; e++) {
                float4 v = ((const float4*)(tile + e * CPIX))[i4];
                float x0 = mm.x ? v.x : 0.f;
                float x1 = mm.y ? v.y : 0.f;
                float x2 = mm.z ? v.z : 0.f;
                float x3 = mm.w ? v.w : 0.f;
                a[e] += (x0 + x1) + (x2 + x3);
                a[16 + e] += fmaf(x0, v.x, fmaf(x1, v.y, fmaf(x2, v.z, x3 * v.w)));
            }
        }
#pragma unroll
        for (int q = 0; q < 33; q++)
#pragma unroll
            for (int off = 16; off > 0; off >>= 1)
                a[q] += __shfl_down_sync(0xFFFFFFFFu, a[q], off);

        if (lane == 0) {
            int ci = (t * CH + ch) * 2 + half;
            float* dst = &g_part[((size_t)bn * NCHK2 + ci) * 33];
#pragma unroll
            for (int q = 0; q < 33; q++) dst[q] = a[q];
        }
    }

    gridbar(1);

    // ================= phase 2: finalize (blocks 0..23) =================
    if (blk < BN) {
        __shared__ float fs[33][8];
        __shared__ float sums[33];
        __shared__ float vm2[Eq];
        int ibn = blk;
        if (tid < 264) {
            int q = tid >> 3, sl = tid & 7;   // q 0..32, slice 0..7
            float s = 0.f;
            for (int c = sl * 18; c < sl * 18 + 18; c++)
                s += g_part[((size_t)ibn * NCHK2 + c) * 33 + q];
            fs[q][sl] = s;
        }
        __syncthreads();
        if (tid < 33) {
            float s = 0.f;
#pragma unroll
            for (int sl = 0; sl < 8; sl++) s += fs[tid][sl];
            sums[tid] = s;
        }
        __syncthreads();
        float cnt = sums[32];
        if (tid < Eq) {
            float mean = sums[tid] / cnt;
            float var  = (sums[16 + tid] - cnt * mean * mean) / (cnt - 1.0f);
            g_w2[ibn * Eq + tid] = var;
            g_w1[ibn * Eq + tid] = -2.0f * var * mean;
            vm2[tid] = var * mean * mean;
        }
        __syncthreads();
        if (tid == 0) {
            float c = 0.f;
#pragma unroll
            for (int e = 0; e < Eq; e++) c += vm2[e];
            g_c[ibn] = c;
            g_cnt[ibn] = cnt;
        }
    }

    gridbar(2);

    // ================= phase 3: errhist (all from smem) =============
    {
        size_t gb = (size_t)bn * NB;
        float w2[Eq], w1[Eq];
#pragma unroll
        for (int e = 0; e < Eq; e++) {
            w2[e] = g_w2[bn * Eq + e];
            w1[e] = g_w1[bn * Eq + e];
        }
        float cc = g_c[bn];

        u32 c0 = 0, cM = 0, s0 = 0, sM = 0;

#pragma unroll
        for (int it = 0; it < HITER; it++) {
            int i4 = ibase + it * 32 + lane;
            u32 mb0 = msk[w * (HITER * 4) + it * 4 + 0];
            u32 mb1 = msk[w * (HITER * 4) + it * 4 + 1];
            u32 mb2 = msk[w * (HITER * 4) + it * 4 + 2];
            u32 mb3 = msk[w * (HITER * 4) + it * 4 + 3];
            int msk4[4] = { (int)((mb0 >> lane) & 1u), (int)((mb1 >> lane) & 1u),
                            (int)((mb2 >> lane) & 1u), (int)((mb3 >> lane) & 1u) };
            float d0 = cc, d1 = cc, d2 = cc, d3 = cc;
#pragma unroll
            for (int e = 0; e < Eq; e++) {
                float4 v = ((const float4*)(tile + e * CPIX))[i4];
                d0 = fmaf(v.x, fmaf(v.x, w2[e], w1[e]), d0);
                d1 = fmaf(v.y, fmaf(v.y, w2[e], w1[e]), d1);
                d2 = fmaf(v.z, fmaf(v.z, w2[e], w1[e]), d2);
                d3 = fmaf(v.w, fmaf(v.w, w2[e], w1[e]), d3);
            }
            float dd[4] = {d0, d1, d2, d3};
#pragma unroll
            for (int j = 0; j < 4; j++) {
                float logit = 2.0f * __expf(-0.5f * dd[j]) - 1.0f;
                float err = msk4[j] ? (1.0f - logit) : (1.0f + logit);
                u32 fx = (u32)(err * FXS + 0.5f);
                int bin = (int)(err * (0.5f * NB));
                if (bin > NB - 1) bin = NB - 1;
                u32 pc = msk4[j] ? 0x10000u : 1u;
                if (bin == 0)           { c0 += pc; s0 += fx; }
                else if (bin == NB - 1) { cM += pc; sM += fx; }
                else {
                    u64 add = (msk4[j] ? (1ull << 47) : (1ull << 30)) | (u64)fx;
                    atomicAdd(&g_hist[gb + bin], add);
                }
            }
        }
#pragma unroll
        for (int off = 16; off > 0; off >>= 1) {
            c0 += __shfl_down_sync(0xFFFFFFFFu, c0, off);
            cM += __shfl_down_sync(0xFFFFFFFFu, cM, off);
            s0 += __shfl_down_sync(0xFFFFFFFFu, s0, off);
            sM += __shfl_down_sync(0xFFFFFFFFu, sM, off);
        }
        if (lane == 0) {
            if (c0)
                atomicAdd(&g_hist[gb + 0],
                    ((u64)(c0 >> 16) << 47) | ((u64)(c0 & 0xFFFFu) << 30) | (u64)s0);
            if (cM)
                atomicAdd(&g_hist[gb + NB - 1],
                    ((u64)(cM >> 16) << 47) | ((u64)(cM & 0xFFFFu) << 30) | (u64)sM);
        }
    }

    gridbar(3);

    // ================= phase 4: Lovász scan (blocks 0..23) ================
    if (blk >= BN) return;
    {
        int ibn = blk;
        float gts = g_cnt[ibn];
        size_t gbase = (size_t)ibn * NB;

        u32 pos[LIT], tot[LIT], fx[LIT];
        u64 tsum = 0ull;
        if (tid < LTH) {
#pragma unroll
            for (int i = 0; i < LIT; i++) {
                int bin = NB - 1 - (tid * LIT + i);
                u64 h = g_hist[gbase + bin];
                pos[i] = (u32)(h >> 47);
                u32 neg = (u32)(h >> 30) & 0x1FFFFu;
                tot[i] = pos[i] + neg;
                fx[i]  = (u32)(h & 0x3FFFFFFFull);
                tsum += ((u64)pos[i] << 32) | (u64)tot[i];
            }
        }

        // hand-rolled exclusive scan over 256 lanes (8 warps)
        __shared__ u64 wtot[8];
        u64 inc = tsum;
        if (tid < LTH) {
#pragma unroll
            for (int off = 1; off < 32; off <<= 1) {
                u64 n = __shfl_up_sync(0xFFFFFFFFu, inc, off);
                if (lane >= off) inc += n;
            }
            if (lane == 31) wtot[w] = inc;
        }
        __syncthreads();
        float loss = 0.f;
        if (tid < LTH) {
            u64 wpref = 0ull;
            for (int ww = 0; ww < w; ww++) wpref += wtot[ww];
            u64 run = wpref + inc - tsum;    // exclusive prefix
#pragma unroll
            for (int i = 0; i < LIT; i++) {
                if (tot[i]) {
                    float cA = (float)(u32)(run >> 32);
                    float kA = (float)(u32)(run & 0xFFFFFFFFull);
                    float cB = cA + (float)pos[i];
                    float kB = kA + (float)tot[i];
                    float JA = 1.0f - (gts - cA) / (gts + kA - cA);
                    float JB = 1.0f - (gts - cB) / (gts + kB - cB);
                    float err_rep = (float)fx[i] / (FXS * (float)tot[i]);
                    loss += err_rep * (JB - JA);
                }
                run += ((u64)pos[i] << 32) | (u64)tot[i];
            }
        }

        __shared__ float red[LTH];
        if (tid < LTH) red[tid] = loss;
        __syncthreads();
        for (int s = LTH / 2; s > 0; s >>= 1) {
            if (tid < s) red[tid] += red[tid + s];
            __syncthreads();
        }

        __shared__ bool is_last;
        if (tid == 0) {
            g_losspart[ibn] = red[0];
            __threadfence();
            int done = atomicAdd(&g_done_l, 1);
            is_last = (done == BN - 1);
        }
        __syncthreads();
        if (is_last && tid == 0) {
            __threadfence();
            float s = 0.f;
#pragma unroll
            for (int i = 0; i < BN; i++) s += g_losspart[i];
            out[0] = s / (float)BN;
            g_done_l = 0;               // reset for next replay
        }
    }
}

extern "C" void kernel_launch(void* const* d_in, const int* in_sizes, int n_in,
                              void* d_out, int out_size) {
    const float* f1 = (const float*)d_in[0];
    const float* f2 = (const float*)d_in[1];
    const int*   gt = (const int*)d_in[2];
    float* out = (float*)d_out;
    cudaFuncSetAttribute(k_fused, cudaFuncAttributeMaxDynamicSharedMemorySize,
                         SMEM_DYN);
    k_fused<<<NBLK, THREADS, SMEM_DYN>>>(f1, f2, gt, out);
}

// round 15
// speedup vs baseline: 3.3188x; 1.0339x over previous
#include <cuda_runtime.h>
#include <cuda_bf16.h>
#include <cstdint>

typedef unsigned int u32;
typedef unsigned long long u64;

// Problem constants
constexpr int Bq = 2, Eq = 16, Hq = 160, Wq = 288, Nq = 12, Tq = 2;
constexpr int HW  = Hq * Wq;            // 46080
constexpr int P   = Tq * HW;            // 92160
constexpr int BN  = Bq * Nq;            // 24 instances

constexpr int CPIX = 1280;              // pixels per chunk (tile)
constexpr int CH   = HW / CPIX;         // 36 chunks per (b,t)
constexpr int NBLK = Bq * Tq * CH;      // 144 blocks (co-resident, 1/SM)
constexpr int NCHK2 = Tq * CH * 2;      // 144 half-chunk partials per instance
constexpr int HITER = 5;                // float4-iters per half-warp
constexpr int THREADS = 768;            // 24 warps: (instance, half)
constexpr int C4 = CPIX / 4;            // 320 float4 per plane

constexpr int NB  = 512;                // histogram bins over err in [0,2]
constexpr float FXS = 4096.0f;          // fixed-point 2^12
// hist packing: (pos<<47) | (neg<<30) | fxsum

constexpr int LTH = 256;                // loss scan lanes
constexpr int LIT = NB / LTH;           // 2 bins per lane

// dynamic smem: float tile[Eq*CPIX] (80KB) + u32 msk[24][HITER*4] (1.92KB)
constexpr int SMEM_DYN = Eq * CPIX * 4 + 24 * HITER * 4 * 4;

// -------- scratch --------
__device__ float g_part[BN * NCHK2 * 33];
__device__ float g_w2[BN * Eq];
__device__ float g_w1[BN * Eq];
__device__ float g_c[BN];
__device__ float g_cnt[BN];
__device__ u64 g_hist[BN * NB];
__device__ float g_losspart[BN];
__device__ int g_sync = 0;              // monotonic grid barrier counter
__device__ int g_done_l = 0;            // loss finalize counter

__device__ __forceinline__ void gridbar(int phase) {
    __syncthreads();
    if (threadIdx.x == 0) {
        __threadfence();
        atomicAdd(&g_sync, 1);
        while (atomicAdd(&g_sync, 0) < phase * NBLK) __nanosleep(64);
    }
    __syncthreads();
}

__global__ void __launch_bounds__(THREADS, 1) k_fused(
    const float* __restrict__ f1, const float* __restrict__ f2,
    const int* __restrict__ gt, float* __restrict__ out) {
    extern __shared__ u32 smem_raw[];
    float* tile = (float*)smem_raw;                 // [Eq][CPIX]
    u32* msk = smem_raw + Eq * CPIX;                // [24][HITER*4]

    int blk = blockIdx.x;
    int tid = threadIdx.x;
    int b = blk / (Tq * CH);
    int r = blk % (Tq * CH);
    int t = r / CH, ch = r % CH;
    int hw0 = ch * CPIX;
    const float* fb = (t ? f2 : f1) + (size_t)b * Eq * HW + hw0;

    // replay-safe counter reset: no block passes barrier1 until all blocks
    // have started, so CAS(3*NBLK -> 0) never races with a spinning block.
    if (tid == 0) atomicCAS(&g_sync, 3 * NBLK, 0);

    // cooperative feat tile load (coalesced float4)
    for (int idx = tid; idx < Eq * C4; idx += THREADS) {
        int e = idx / C4, i = idx - e * C4;
        ((float4*)(tile + e * CPIX))[i] = ((const float4*)(fb + (size_t)e * HW))[i];
    }

    // zero hist slice (completion covered by barrier 1)
    for (int i = blk * THREADS + tid; i < BN * NB; i += NBLK * THREADS)
        g_hist[i] = 0ull;
    __syncthreads();

    int w = tid >> 5, lane = tid & 31;
    int inst = w % Nq;                  // instance
    int half = w / Nq;                  // 0/1: pixel half of the tile
    int bn = b * Nq + inst;
    const int4* gt4 = (const int4*)(gt + ((size_t)bn * Tq + t) * HW + hw0);
    int ibase = half * (HITER * 32);    // float4 units

    // ================= phase 1: stats (+ cache gt ballots) =================
    {
        float a[33];
#pragma unroll
        for (int q = 0; q < 33; q++) a[q] = 0.f;

#pragma unroll
        for (int it = 0; it < HITER; it++) {
            int i4 = ibase + it * 32 + lane;
            int4 mm = gt4[i4];
            u32 b0 = __ballot_sync(0xFFFFFFFFu, mm.x);
            u32 b1 = __ballot_sync(0xFFFFFFFFu, mm.y);
            u32 b2 = __ballot_sync(0xFFFFFFFFu, mm.z);
            u32 b3 = __ballot_sync(0xFFFFFFFFu, mm.w);
            if (lane == 0) {
                msk[w * (HITER * 4) + it * 4 + 0] = b0;
                msk[w * (HITER * 4) + it * 4 + 1] = b1;
                msk[w * (HITER * 4) + it * 4 + 2] = b2;
                msk[w * (HITER * 4) + it * 4 + 3] = b3;
            }
            a[32] += (float)(mm.x + mm.y + mm.z + mm.w);
#pragma unroll
            for (int e = 0; e < Eq; e++) {
                float4 v = ((const float4*)(tile + e * CPIX))[i4];
                float x0 = mm.x ? v.x : 0.f;
                float x1 = mm.y ? v.y : 0.f;
                float x2 = mm.z ? v.z : 0.f;
                float x3 = mm.w ? v.w : 0.f;
                a[e] += (x0 + x1) + (x2 + x3);
                a[16 + e] += fmaf(x0, v.x, fmaf(x1, v.y, fmaf(x2, v.z, x3 * v.w)));
            }
        }
#pragma unroll
        for (int q = 0; q < 33; q++)
#pragma unroll
            for (int off = 16; off > 0; off >>= 1)
                a[q] += __shfl_down_sync(0xFFFFFFFFu, a[q], off);

        if (lane == 0) {
            int ci = (t * CH + ch) * 2 + half;
            float* dst = &g_part[((size_t)bn * NCHK2 + ci) * 33];
#pragma unroll
            for (int q = 0; q < 33; q++) dst[q] = a[q];
        }
    }

    gridbar(1);

    // ================= phase 2: finalize (blocks 0..23) =================
    if (blk < BN) {
        __shared__ float fs[33][8];
        __shared__ float sums[33];
        __shared__ float vm2[Eq];
        int ibn = blk;
        if (tid < 264) {
            int q = tid >> 3, sl = tid & 7;   // q 0..32, slice 0..7
            float s = 0.f;
            for (int c = sl * 18; c < sl * 18 + 18; c++)
                s += g_part[((size_t)ibn * NCHK2 + c) * 33 + q];
            fs[q][sl] = s;
        }
        __syncthreads();
        if (tid < 33) {
            float s = 0.f;
#pragma unroll
            for (int sl = 0; sl < 8; sl++) s += fs[tid][sl];
            sums[tid] = s;
        }
        __syncthreads();
        float cnt = sums[32];
        if (tid < Eq) {
            float mean = sums[tid] / cnt;
            float var  = (sums[16 + tid] - cnt * mean * mean) / (cnt - 1.0f);
            g_w2[ibn * Eq + tid] = var;
            g_w1[ibn * Eq + tid] = -2.0f * var * mean;
            vm2[tid] = var * mean * mean;
        }
        __syncthreads();
        if (tid == 0) {
            float c = 0.f;
#pragma unroll
            for (int e = 0; e < Eq; e++) c += vm2[e];
            g_c[ibn] = c;
            g_cnt[ibn] = cnt;
        }
    }

    gridbar(2);

    // ================= phase 3: errhist (all from smem, branchless) =======
    {
        size_t gb = (size_t)bn * NB;
        float w2[Eq], w1[Eq];
#pragma unroll
        for (int e = 0; e < Eq; e++) {
            w2[e] = g_w2[bn * Eq + e];
            w1[e] = g_w1[bn * Eq + e];
        }
        float cc = g_c[bn];

        u32 c0 = 0, cM = 0, s0 = 0, sM = 0;

#pragma unroll
        for (int it = 0; it < HITER; it++) {
            int i4 = ibase + it * 32 + lane;
            u32 mb0 = msk[w * (HITER * 4) + it * 4 + 0];
            u32 mb1 = msk[w * (HITER * 4) + it * 4 + 1];
            u32 mb2 = msk[w * (HITER * 4) + it * 4 + 2];
            u32 mb3 = msk[w * (HITER * 4) + it * 4 + 3];
            int msk4[4] = { (int)((mb0 >> lane) & 1u), (int)((mb1 >> lane) & 1u),
                            (int)((mb2 >> lane) & 1u), (int)((mb3 >> lane) & 1u) };
            // two half-chains per pixel for 2x ILP on the FFMA dependency
            float a0 = cc, a1 = cc, a2 = cc, a3 = cc;
            float e0 = 0.f, e1 = 0.f, e2 = 0.f, e3 = 0.f;
#pragma unroll
            for (int e = 0; e < 8; e++) {
                float4 v = ((const float4*)(tile + e * CPIX))[i4];
                a0 = fmaf(v.x, fmaf(v.x, w2[e], w1[e]), a0);
                a1 = fmaf(v.y, fmaf(v.y, w2[e], w1[e]), a1);
                a2 = fmaf(v.z, fmaf(v.z, w2[e], w1[e]), a2);
                a3 = fmaf(v.w, fmaf(v.w, w2[e], w1[e]), a3);
            }
#pragma unroll
            for (int e = 8; e < Eq; e++) {
                float4 v = ((const float4*)(tile + e * CPIX))[i4];
                e0 = fmaf(v.x, fmaf(v.x, w2[e], w1[e]), e0);
                e1 = fmaf(v.y, fmaf(v.y, w2[e], w1[e]), e1);
                e2 = fmaf(v.z, fmaf(v.z, w2[e], w1[e]), e2);
                e3 = fmaf(v.w, fmaf(v.w, w2[e], w1[e]), e3);
            }
            float dd[4] = {a0 + e0, a1 + e1, a2 + e2, a3 + e3};
#pragma unroll
            for (int j = 0; j < 4; j++) {
                float logit = 2.0f * __expf(-0.5f * dd[j]) - 1.0f;
                float err = msk4[j] ? (1.0f - logit) : (1.0f + logit);
                u32 fx = (u32)(err * FXS + 0.5f);
                int bin = (int)(err * (0.5f * NB));
                if (bin > NB - 1) bin = NB - 1;
                u32 pc = msk4[j] ? 0x10000u : 1u;
                // branchless edge accumulation
                bool lo = (bin == 0), hi = (bin == NB - 1);
                c0 += lo ? pc : 0u;  s0 += lo ? fx : 0u;
                cM += hi ? pc : 0u;  sM += hi ? fx : 0u;
                // predicated mid-bin atomic (single guarded instruction)
                if (!lo && !hi) {
                    u64 add = (msk4[j] ? (1ull << 47) : (1ull << 30)) | (u64)fx;
                    atomicAdd(&g_hist[gb + bin], add);
                }
            }
        }
#pragma unroll
        for (int off = 16; off > 0; off >>= 1) {
            c0 += __shfl_down_sync(0xFFFFFFFFu, c0, off);
            cM += __shfl_down_sync(0xFFFFFFFFu, cM, off);
            s0 += __shfl_down_sync(0xFFFFFFFFu, s0, off);
            sM += __shfl_down_sync(0xFFFFFFFFu, sM, off);
        }
        if (lane == 0) {
            if (c0)
                atomicAdd(&g_hist[gb + 0],
                    ((u64)(c0 >> 16) << 47) | ((u64)(c0 & 0xFFFFu) << 30) | (u64)s0);
            if (cM)
                atomicAdd(&g_hist[gb + NB - 1],
                    ((u64)(cM >> 16) << 47) | ((u64)(cM & 0xFFFFu) << 30) | (u64)sM);
        }
    }

    gridbar(3);

    // ================= phase 4: Lovász scan (blocks 0..23) ================
    if (blk >= BN) return;
    {
        int ibn = blk;
        float gts = g_cnt[ibn];
        size_t gbase = (size_t)ibn * NB;

        u32 pos[LIT], tot[LIT], fx[LIT];
        u64 tsum = 0ull;
        if (tid < LTH) {
#pragma unroll
            for (int i = 0; i < LIT; i++) {
                int bin = NB - 1 - (tid * LIT + i);
                u64 h = g_hist[gbase + bin];
                pos[i] = (u32)(h >> 47);
                u32 neg = (u32)(h >> 30) & 0x1FFFFu;
                tot[i] = pos[i] + neg;
                fx[i]  = (u32)(h & 0x3FFFFFFFull);
                tsum += ((u64)pos[i] << 32) | (u64)tot[i];
            }
        }

        // hand-rolled exclusive scan over 256 lanes (8 warps)
        __shared__ u64 wtot[8];
        u64 inc = tsum;
        if (tid < LTH) {
#pragma unroll
            for (int off = 1; off < 32; off <<= 1) {
                u64 n = __shfl_up_sync(0xFFFFFFFFu, inc, off);
                if (lane >= off) inc += n;
            }
            if (lane == 31) wtot[w] = inc;
        }
        __syncthreads();
        float loss = 0.f;
        if (tid < LTH) {
            u64 wpref = 0ull;
            for (int ww = 0; ww < w; ww++) wpref += wtot[ww];
            u64 run = wpref + inc - tsum;    // exclusive prefix
#pragma unroll
            for (int i = 0; i < LIT; i++) {
                if (tot[i]) {
                    float cA = (float)(u32)(run >> 32);
                    float kA = (float)(u32)(run & 0xFFFFFFFFull);
                    float cB = cA + (float)pos[i];
                    float kB = kA + (float)tot[i];
                    float JA = 1.0f - (gts - cA) / (gts + kA - cA);
                    float JB = 1.0f - (gts - cB) / (gts + kB - cB);
                    float err_rep = (float)fx[i] / (FXS * (float)tot[i]);
                    loss += err_rep * (JB - JA);
                }
                run += ((u64)pos[i] << 32) | (u64)tot[i];
            }
        }

        __shared__ float red[LTH];
        if (tid < LTH) red[tid] = loss;
        __syncthreads();
        for (int s = LTH / 2; s > 0; s >>= 1) {
            if (tid < s) red[tid] += red[tid + s];
            __syncthreads();
        }

        __shared__ bool is_last;
        if (tid == 0) {
            g_losspart[ibn] = red[0];
            __threadfence();
            int done = atomicAdd(&g_done_l, 1);
            is_last = (done == BN - 1);
        }
        __syncthreads();
        if (is_last && tid == 0) {
            __threadfence();
            float s = 0.f;
#pragma unroll
            for (int i = 0; i < BN; i++) s += g_losspart[i];
            out[0] = s / (float)BN;
            g_done_l = 0;               // reset for next replay
        }
    }
}

extern "C" void kernel_launch(void* const* d_in, const int* in_sizes, int n_in,
                              void* d_out, int out_size) {
    const float* f1 = (const float*)d_in[0];
    const float* f2 = (const float*)d_in[1];
    const int*   gt = (const int*)d_in[2];
    float* out = (float*)d_out;
    cudaFuncSetAttribute(k_fused, cudaFuncAttributeMaxDynamicSharedMemorySize,
                         SMEM_DYN);
    k_fused<<<NBLK, THREADS, SMEM_DYN>>>(f1, f2, gt, out);
}

// round 16
// speedup vs baseline: 3.4526x; 1.0403x over previous
#include <cuda_runtime.h>
#include <cuda_bf16.h>
#include <cstdint>

typedef unsigned int u32;
typedef unsigned long long u64;

// Problem constants
constexpr int Bq = 2, Eq = 16, Hq = 160, Wq = 288, Nq = 12, Tq = 2;
constexpr int HW  = Hq * Wq;            // 46080
constexpr int P   = Tq * HW;            // 92160
constexpr int BN  = Bq * Nq;            // 24 instances

constexpr int CPIX = 1280;              // pixels per chunk (tile)
constexpr int CH   = HW / CPIX;         // 36 chunks per (b,t)
constexpr int NBLK = Bq * Tq * CH;      // 144 blocks (co-resident, 1/SM)
constexpr int NCHK2 = Tq * CH * 2;      // 144 half-chunk partials per instance
constexpr int HITER = 5;                // float4-iters per half-warp
constexpr int THREADS = 768;            // 24 warps: (instance, half)
constexpr int C4 = CPIX / 4;            // 320 float4 per plane

constexpr int NB  = 512;                // histogram bins over err in [0,2]
constexpr float FXS = 4096.0f;          // fixed-point 2^12
// hist packing: (pos<<47) | (neg<<30) | fxsum

constexpr int LTH = 256;                // loss scan lanes
constexpr int LIT = NB / LTH;           // 2 bins per lane

// dynamic smem: float tile[Eq*CPIX] (80KB)
constexpr int SMEM_DYN = Eq * CPIX * 4;

// -------- packed f32x2 helpers --------
__device__ __forceinline__ u64 pack2(float lo, float hi) {
    u64 r; asm("mov.b64 %0, {%1,%2};" : "=l"(r) : "f"(lo), "f"(hi)); return r;
}
__device__ __forceinline__ void unpack2(u64 v, float& lo, float& hi) {
    asm("mov.b64 {%0,%1}, %2;" : "=f"(lo), "=f"(hi) : "l"(v));
}
__device__ __forceinline__ u64 fma2(u64 a, u64 b, u64 c) {
    u64 d; asm("fma.rn.f32x2 %0, %1, %2, %3;" : "=l"(d) : "l"(a), "l"(b), "l"(c));
    return d;
}

// -------- scratch --------
__device__ float g_part[BN * NCHK2 * 33];
__device__ float g_w2[BN * Eq];
__device__ float g_w1[BN * Eq];
__device__ float g_c[BN];
__device__ float g_cnt[BN];
__device__ u64 g_hist[BN * NB];
__device__ float g_losspart[BN];
__device__ int g_sync = 0;              // monotonic grid barrier counter
__device__ int g_done_l = 0;            // loss finalize counter

__device__ __forceinline__ void gridbar(int phase) {
    __syncthreads();
    if (threadIdx.x == 0) {
        __threadfence();
        atomicAdd(&g_sync, 1);
        while (atomicAdd(&g_sync, 0) < phase * NBLK) __nanosleep(64);
    }
    __syncthreads();
}

__global__ void __launch_bounds__(THREADS, 1) k_fused(
    const float* __restrict__ f1, const float* __restrict__ f2,
    const int* __restrict__ gt, float* __restrict__ out) {
    extern __shared__ u32 smem_raw[];
    float* tile = (float*)smem_raw;                 // [Eq][CPIX]

    int blk = blockIdx.x;
    int tid = threadIdx.x;
    int b = blk / (Tq * CH);
    int r = blk % (Tq * CH);
    int t = r / CH, ch = r % CH;
    int hw0 = ch * CPIX;
    const float* fb = (t ? f2 : f1) + (size_t)b * Eq * HW + hw0;

    // replay-safe counter reset: no block passes barrier1 until all blocks
    // have started, so CAS(3*NBLK -> 0) never races with a spinning block.
    if (tid == 0) atomicCAS(&g_sync, 3 * NBLK, 0);

    // cooperative feat tile load (coalesced float4)
    for (int idx = tid; idx < Eq * C4; idx += THREADS) {
        int e = idx / C4, i = idx - e * C4;
        ((float4*)(tile + e * CPIX))[i] = ((const float4*)(fb + (size_t)e * HW))[i];
    }

    // zero hist slice (completion covered by barrier 1)
    for (int i = blk * THREADS + tid; i < BN * NB; i += NBLK * THREADS)
        g_hist[i] = 0ull;
    __syncthreads();

    int w = tid >> 5, lane = tid & 31;
    int inst = w % Nq;                  // instance
    int half = w / Nq;                  // 0/1: pixel half of the tile
    int bn = b * Nq + inst;
    const int4* gt4 = (const int4*)(gt + ((size_t)bn * Tq + t) * HW + hw0);
    int ibase = half * (HITER * 32);    // float4 units

    // ================= phase 1: stats =================
    {
        float a[33];
#pragma unroll
        for (int q = 0; q < 33; q++) a[q] = 0.f;

#pragma unroll
        for (int it = 0; it < HITER; it++) {
            int i4 = ibase + it * 32 + lane;
            int4 mm = gt4[i4];
            a[32] += (float)(mm.x + mm.y + mm.z + mm.w);
#pragma unroll
            for (int e = 0; e < Eq; e++) {
                float4 v = ((const float4*)(tile + e * CPIX))[i4];
                float x0 = mm.x ? v.x : 0.f;
                float x1 = mm.y ? v.y : 0.f;
                float x2 = mm.z ? v.z : 0.f;
                float x3 = mm.w ? v.w : 0.f;
                a[e] += (x0 + x1) + (x2 + x3);
                a[16 + e] += fmaf(x0, v.x, fmaf(x1, v.y, fmaf(x2, v.z, x3 * v.w)));
            }
        }
#pragma unroll
        for (int q = 0; q < 33; q++)
#pragma unroll
            for (int off = 16; off > 0; off >>= 1)
                a[q] += __shfl_down_sync(0xFFFFFFFFu, a[q], off);

        if (lane == 0) {
            int ci = (t * CH + ch) * 2 + half;
            float* dst = &g_part[((size_t)bn * NCHK2 + ci) * 33];
#pragma unroll
            for (int q = 0; q < 33; q++) dst[q] = a[q];
        }
    }

    gridbar(1);

    // ================= phase 2: finalize (blocks 0..23) =================
    if (blk < BN) {
        __shared__ float fs[33][8];
        __shared__ float sums[33];
        __shared__ float vm2[Eq];
        int ibn = blk;
        if (tid < 264) {
            int q = tid >> 3, sl = tid & 7;   // q 0..32, slice 0..7
            float s = 0.f;
            for (int c = sl * 18; c < sl * 18 + 18; c++)
                s += g_part[((size_t)ibn * NCHK2 + c) * 33 + q];
            fs[q][sl] = s;
        }
        __syncthreads();
        if (tid < 33) {
            float s = 0.f;
#pragma unroll
            for (int sl = 0; sl < 8; sl++) s += fs[tid][sl];
            sums[tid] = s;
        }
        __syncthreads();
        float cnt = sums[32];
        if (tid < Eq) {
            float mean = sums[tid] / cnt;
            float var  = (sums[16 + tid] - cnt * mean * mean) / (cnt - 1.0f);
            g_w2[ibn * Eq + tid] = var;
            g_w1[ibn * Eq + tid] = -2.0f * var * mean;
            vm2[tid] = var * mean * mean;
        }
        __syncthreads();
        if (tid == 0) {
            float c = 0.f;
#pragma unroll
            for (int e = 0; e < Eq; e++) c += vm2[e];
            g_c[ibn] = c;
            g_cnt[ibn] = cnt;
        }
    }

    gridbar(2);

    // ========== phase 3: errhist — packed f32x2, group-interchanged =======
    {
        size_t gb = (size_t)bn * NB;
        float cc = g_c[bn];

        // packed accumulators for 5 iters x (px01, px23)
        u64 d01[HITER], d23[HITER];
        u64 cc2 = pack2(cc, 0.f);       // cc added once (to px0 lane of d01)
#pragma unroll
        for (int it = 0; it < HITER; it++) { d01[it] = 0ull; d23[it] = 0ull; }

        // two plane groups: weights live only within a group (32 regs)
#pragma unroll
        for (int g = 0; g < 2; g++) {
            u64 W2[8], W1[8];
#pragma unroll
            for (int k = 0; k < 8; k++) {
                float w2s = g_w2[bn * Eq + g * 8 + k];
                float w1s = g_w1[bn * Eq + g * 8 + k];
                W2[k] = pack2(w2s, w2s);
                W1[k] = pack2(w1s, w1s);
            }
#pragma unroll
            for (int it = 0; it < HITER; it++) {
                int i4 = ibase + it * 32 + lane;
#pragma unroll
                for (int k = 0; k < 8; k++) {
                    int e = g * 8 + k;
                    ulonglong2 vv = ((const ulonglong2*)(tile + e * CPIX))[i4];
                    d01[it] = fma2(vv.x, fma2(vv.x, W2[k], W1[k]), d01[it]);
                    d23[it] = fma2(vv.y, fma2(vv.y, W2[k], W1[k]), d23[it]);
                }
            }
        }

        u32 c0 = 0, cM = 0, s0 = 0, sM = 0;

#pragma unroll
        for (int it = 0; it < HITER; it++) {
            int i4 = ibase + it * 32 + lane;
            int4 mm = gt4[i4];          // L1-warm reload
            float dd[4];
            unpack2(d01[it], dd[0], dd[1]);
            unpack2(d23[it], dd[2], dd[3]);
            int msk4[4] = {mm.x, mm.y, mm.z, mm.w};
#pragma unroll
            for (int j = 0; j < 4; j++) {
                float logit = 2.0f * __expf(-0.5f * (dd[j] + cc)) - 1.0f;
                float err = msk4[j] ? (1.0f - logit) : (1.0f + logit);
                u32 fx = (u32)(err * FXS + 0.5f);
                int bin = (int)(err * (0.5f * NB));
                if (bin > NB - 1) bin = NB - 1;
                u32 pc = msk4[j] ? 0x10000u : 1u;
                bool lo = (bin == 0), hi = (bin == NB - 1);
                c0 += lo ? pc : 0u;  s0 += lo ? fx : 0u;
                cM += hi ? pc : 0u;  sM += hi ? fx : 0u;
                if (!lo && !hi) {
                    u64 add = (msk4[j] ? (1ull << 47) : (1ull << 30)) | (u64)fx;
                    atomicAdd(&g_hist[gb + bin], add);
                }
            }
        }
#pragma unroll
        for (int off = 16; off > 0; off >>= 1) {
            c0 += __shfl_down_sync(0xFFFFFFFFu, c0, off);
            cM += __shfl_down_sync(0xFFFFFFFFu, cM, off);
            s0 += __shfl_down_sync(0xFFFFFFFFu, s0, off);
            sM += __shfl_down_sync(0xFFFFFFFFu, sM, off);
        }
        if (lane == 0) {
            if (c0)
                atomicAdd(&g_hist[gb + 0],
                    ((u64)(c0 >> 16) << 47) | ((u64)(c0 & 0xFFFFu) << 30) | (u64)s0);
            if (cM)
                atomicAdd(&g_hist[gb + NB - 1],
                    ((u64)(cM >> 16) << 47) | ((u64)(cM & 0xFFFFu) << 30) | (u64)sM);
        }
        (void)cc2;
    }

    gridbar(3);

    // ================= phase 4: Lovász scan (blocks 0..23) ================
    if (blk >= BN) return;
    {
        int ibn = blk;
        float gts = g_cnt[ibn];
        size_t gbase = (size_t)ibn * NB;

        u32 pos[LIT], tot[LIT], fx[LIT];
        u64 tsum = 0ull;
        if (tid < LTH) {
#pragma unroll
            for (int i = 0; i < LIT; i++) {
                int bin = NB - 1 - (tid * LIT + i);
                u64 h = g_hist[gbase + bin];
                pos[i] = (u32)(h >> 47);
                u32 neg = (u32)(h >> 30) & 0x1FFFFu;
                tot[i] = pos[i] + neg;
                fx[i]  = (u32)(h & 0x3FFFFFFFull);
                tsum += ((u64)pos[i] << 32) | (u64)tot[i];
            }
        }

        // hand-rolled exclusive scan over 256 lanes (8 warps)
        __shared__ u64 wtot[8];
        u64 inc = tsum;
        if (tid < LTH) {
#pragma unroll
            for (int off = 1; off < 32; off <<= 1) {
                u64 n = __shfl_up_sync(0xFFFFFFFFu, inc, off);
                if (lane >= off) inc += n;
            }
            if (lane == 31) wtot[w] = inc;
        }
        __syncthreads();
        float loss = 0.f;
        if (tid < LTH) {
            u64 wpref = 0ull;
            for (int ww = 0; ww < w; ww++) wpref += wtot[ww];
            u64 run = wpref + inc - tsum;    // exclusive prefix
#pragma unroll
            for (int i = 0; i < LIT; i++) {
                if (tot[i]) {
                    float cA = (float)(u32)(run >> 32);
                    float kA = (float)(u32)(run & 0xFFFFFFFFull);
                    float cB = cA + (float)pos[i];
                    float kB = kA + (float)tot[i];
                    float JA = 1.0f - (gts - cA) / (gts + kA - cA);
                    float JB = 1.0f - (gts - cB) / (gts + kB - cB);
                    float err_rep = (float)fx[i] / (FXS * (float)tot[i]);
                    loss += err_rep * (JB - JA);
                }
                run += ((u64)pos[i] << 32) | (u64)tot[i];
            }
        }

        __shared__ float red[LTH];
        if (tid < LTH) red[tid] = loss;
        __syncthreads();
        for (int s = LTH / 2; s > 0; s >>= 1) {
            if (tid < s) red[tid] += red[tid + s];
            __syncthreads();
        }

        __shared__ bool is_last;
        if (tid == 0) {
            g_losspart[ibn] = red[0];
            __threadfence();
            int done = atomicAdd(&g_done_l, 1);
            is_last = (done == BN - 1);
        }
        __syncthreads();
        if (is_last && tid == 0) {
            __threadfence();
            float s = 0.f;
#pragma unroll
            for (int i = 0; i < BN; i++) s += g_losspart[i];
            out[0] = s / (float)BN;
            g_done_l = 0;               // reset for next replay
        }
    }
}

extern "C" void kernel_launch(void* const* d_in, const int* in_sizes, int n_in,
                              void* d_out, int out_size) {
    const float* f1 = (const float*)d_in[0];
    const float* f2 = (const float*)d_in[1];
    const int*   gt = (const int*)d_in[2];
    float* out = (float*)d_out;
    cudaFuncSetAttribute(k_fused, cudaFuncAttributeMaxDynamicSharedMemorySize,
                         SMEM_DYN);
    k_fused<<<NBLK, THREADS, SMEM_DYN>>>(f1, f2, gt, out);
}

// round 17
// speedup vs baseline: 4.0039x; 1.1597x over previous
#include <cuda_runtime.h>
#include <cuda_bf16.h>
#include <cstdint>

typedef unsigned int u32;
typedef unsigned long long u64;

// Problem constants
constexpr int Bq = 2, Eq = 16, Hq = 160, Wq = 288, Nq = 12, Tq = 2;
constexpr int HW  = Hq * Wq;            // 46080
constexpr int P   = Tq * HW;            // 92160
constexpr int BN  = Bq * Nq;            // 24 instances

constexpr int CPIX = 1280;              // pixels per chunk (tile)
constexpr int CH   = HW / CPIX;         // 36 chunks per (b,t)
constexpr int NBLK = Bq * Tq * CH;      // 144 blocks (co-resident, 1/SM)
constexpr int NCHK2 = Tq * CH * 2;      // 144 half-chunk partials per instance
constexpr int HITER = 5;                // float4-iters per half-warp
constexpr int THREADS = 768;            // 24 warps: (instance, half)
constexpr int C4 = CPIX / 4;            // 320 float4 per plane

constexpr int NB  = 256;                // histogram bins over err in [0,2]
constexpr float FXS = 4096.0f;          // fixed-point 2^12
// hist packing: (pos<<47) | (neg<<30) | fxsum

constexpr int LTH = 256;                // loss scan lanes, 1 bin per lane

// dynamic smem: float tile[Eq*CPIX] (80KB) + u64 shist[Nq*NB] (24KB)
constexpr int SMEM_DYN = Eq * CPIX * 4 + Nq * NB * 8;

// -------- packed f32x2 helpers --------
__device__ __forceinline__ u64 pack2(float lo, float hi) {
    u64 r; asm("mov.b64 %0, {%1,%2};" : "=l"(r) : "f"(lo), "f"(hi)); return r;
}
__device__ __forceinline__ void unpack2(u64 v, float& lo, float& hi) {
    asm("mov.b64 {%0,%1}, %2;" : "=f"(lo), "=f"(hi) : "l"(v));
}
__device__ __forceinline__ u64 fma2(u64 a, u64 b, u64 c) {
    u64 d; asm("fma.rn.f32x2 %0, %1, %2, %3;" : "=l"(d) : "l"(a), "l"(b), "l"(c));
    return d;
}

// -------- scratch --------
__device__ float g_part[BN * NCHK2 * 33];
__device__ float g_w2[BN * Eq];
__device__ float g_w1[BN * Eq];
__device__ float g_c[BN];
__device__ float g_cnt[BN];
__device__ u64 g_hist[BN * NB];
__device__ float g_losspart[BN];
__device__ int g_sync = 0;              // monotonic grid barrier counter
__device__ int g_done_l = 0;            // loss finalize counter

__device__ __forceinline__ void gridbar(int phase) {
    __syncthreads();
    if (threadIdx.x == 0) {
        __threadfence();
        atomicAdd(&g_sync, 1);
        while (atomicAdd(&g_sync, 0) < phase * NBLK) __nanosleep(64);
    }
    __syncthreads();
}

__global__ void __launch_bounds__(THREADS, 1) k_fused(
    const float* __restrict__ f1, const float* __restrict__ f2,
    const int* __restrict__ gt, float* __restrict__ out) {
    extern __shared__ u32 smem_raw[];
    float* tile = (float*)smem_raw;                     // [Eq][CPIX]
    u64* shist = (u64*)(smem_raw + Eq * CPIX);          // [Nq][NB]

    int blk = blockIdx.x;
    int tid = threadIdx.x;
    int b = blk / (Tq * CH);
    int r = blk % (Tq * CH);
    int t = r / CH, ch = r % CH;
    int hw0 = ch * CPIX;
    const float* fb = (t ? f2 : f1) + (size_t)b * Eq * HW + hw0;

    // replay-safe counter reset: no block passes barrier1 until all blocks
    // have started, so CAS(3*NBLK -> 0) never races with a spinning block.
    if (tid == 0) atomicCAS(&g_sync, 3 * NBLK, 0);

    // cooperative feat tile load (coalesced float4) + smem hist zero
    for (int idx = tid; idx < Eq * C4; idx += THREADS) {
        int e = idx / C4, i = idx - e * C4;
        ((float4*)(tile + e * CPIX))[i] = ((const float4*)(fb + (size_t)e * HW))[i];
    }
    for (int i = tid; i < Nq * NB; i += THREADS) shist[i] = 0ull;

    // zero global hist slice (completion covered by barrier 1)
    for (int i = blk * THREADS + tid; i < BN * NB; i += NBLK * THREADS)
        g_hist[i] = 0ull;
    __syncthreads();

    int w = tid >> 5, lane = tid & 31;
    int inst = w % Nq;                  // instance
    int half = w / Nq;                  // 0/1: pixel half of the tile
    int bn = b * Nq + inst;
    const int4* gt4 = (const int4*)(gt + ((size_t)bn * Tq + t) * HW + hw0);
    int ibase = half * (HITER * 32);    // float4 units

    // ================= phase 1: stats =================
    {
        float a[33];
#pragma unroll
        for (int q = 0; q < 33; q++) a[q] = 0.f;

#pragma unroll
        for (int it = 0; it < HITER; it++) {
            int i4 = ibase + it * 32 + lane;
            int4 mm = gt4[i4];
            a[32] += (float)(mm.x + mm.y + mm.z + mm.w);
#pragma unroll
            for (int e = 0; e < Eq; e++) {
                float4 v = ((const float4*)(tile + e * CPIX))[i4];
                float x0 = mm.x ? v.x : 0.f;
                float x1 = mm.y ? v.y : 0.f;
                float x2 = mm.z ? v.z : 0.f;
                float x3 = mm.w ? v.w : 0.f;
                a[e] += (x0 + x1) + (x2 + x3);
                a[16 + e] += fmaf(x0, v.x, fmaf(x1, v.y, fmaf(x2, v.z, x3 * v.w)));
            }
        }
#pragma unroll
        for (int q = 0; q < 33; q++)
#pragma unroll
            for (int off = 16; off > 0; off >>= 1)
                a[q] += __shfl_down_sync(0xFFFFFFFFu, a[q], off);

        if (lane == 0) {
            int ci = (t * CH + ch) * 2 + half;
            float* dst = &g_part[((size_t)bn * NCHK2 + ci) * 33];
#pragma unroll
            for (int q = 0; q < 33; q++) dst[q] = a[q];
        }
    }

    gridbar(1);

    // ================= phase 2: finalize (blocks 0..23) =================
    if (blk < BN) {
        __shared__ float fs[33][8];
        __shared__ float sums[33];
        __shared__ float vm2[Eq];
        int ibn = blk;
        if (tid < 264) {
            int q = tid >> 3, sl = tid & 7;   // q 0..32, slice 0..7
            float s = 0.f;
            for (int c = sl * 18; c < sl * 18 + 18; c++)
                s += g_part[((size_t)ibn * NCHK2 + c) * 33 + q];
            fs[q][sl] = s;
        }
        __syncthreads();
        if (tid < 33) {
            float s = 0.f;
#pragma unroll
            for (int sl = 0; sl < 8; sl++) s += fs[tid][sl];
            sums[tid] = s;
        }
        __syncthreads();
        float cnt = sums[32];
        if (tid < Eq) {
            float mean = sums[tid] / cnt;
            float var  = (sums[16 + tid] - cnt * mean * mean) / (cnt - 1.0f);
            g_w2[ibn * Eq + tid] = var;
            g_w1[ibn * Eq + tid] = -2.0f * var * mean;
            vm2[tid] = var * mean * mean;
        }
        __syncthreads();
        if (tid == 0) {
            float c = 0.f;
#pragma unroll
            for (int e = 0; e < Eq; e++) c += vm2[e];
            g_c[ibn] = c;
            g_cnt[ibn] = cnt;
        }
    }

    gridbar(2);

    // ========== phase 3: errhist — f32x2 math, smem mid-bin hist ==========
    {
        float cc = g_c[bn];

        // packed accumulators for 5 iters x (px01, px23)
        u64 d01[HITER], d23[HITER];
#pragma unroll
        for (int it = 0; it < HITER; it++) { d01[it] = 0ull; d23[it] = 0ull; }

        // two plane groups: weights live only within a group (32 regs)
#pragma unroll
        for (int g = 0; g < 2; g++) {
            u64 W2[8], W1[8];
#pragma unroll
            for (int k = 0; k < 8; k++) {
                float w2s = g_w2[bn * Eq + g * 8 + k];
                float w1s = g_w1[bn * Eq + g * 8 + k];
                W2[k] = pack2(w2s, w2s);
                W1[k] = pack2(w1s, w1s);
            }
#pragma unroll
            for (int it = 0; it < HITER; it++) {
                int i4 = ibase + it * 32 + lane;
#pragma unroll
                for (int k = 0; k < 8; k++) {
                    int e = g * 8 + k;
                    ulonglong2 vv = ((const ulonglong2*)(tile + e * CPIX))[i4];
                    d01[it] = fma2(vv.x, fma2(vv.x, W2[k], W1[k]), d01[it]);
                    d23[it] = fma2(vv.y, fma2(vv.y, W2[k], W1[k]), d23[it]);
                }
            }
        }

        u32 c0 = 0, cM = 0, s0 = 0, sM = 0;
        u64* hrow = shist + inst * NB;

#pragma unroll
        for (int it = 0; it < HITER; it++) {
            int i4 = ibase + it * 32 + lane;
            int4 mm = gt4[i4];          // L1-warm reload
            float dd[4];
            unpack2(d01[it], dd[0], dd[1]);
            unpack2(d23[it], dd[2], dd[3]);
            int msk4[4] = {mm.x, mm.y, mm.z, mm.w};
#pragma unroll
            for (int j = 0; j < 4; j++) {
                float logit = 2.0f * __expf(-0.5f * (dd[j] + cc)) - 1.0f;
                float err = msk4[j] ? (1.0f - logit) : (1.0f + logit);
                u32 fx = (u32)(err * FXS + 0.5f);
                int bin = (int)(err * (0.5f * NB));
                if (bin > NB - 1) bin = NB - 1;
                u32 pc = msk4[j] ? 0x10000u : 1u;
                bool lo = (bin == 0), hi = (bin == NB - 1);
                c0 += lo ? pc : 0u;  s0 += lo ? fx : 0u;
                cM += hi ? pc : 0u;  sM += hi ? fx : 0u;
                if (!lo && !hi) {
                    u64 add = (msk4[j] ? (1ull << 47) : (1ull << 30)) | (u64)fx;
                    atomicAdd(&hrow[bin], add);
                }
            }
        }
#pragma unroll
        for (int off = 16; off > 0; off >>= 1) {
            c0 += __shfl_down_sync(0xFFFFFFFFu, c0, off);
            cM += __shfl_down_sync(0xFFFFFFFFu, cM, off);
            s0 += __shfl_down_sync(0xFFFFFFFFu, s0, off);
            sM += __shfl_down_sync(0xFFFFFFFFu, sM, off);
        }
        if (lane == 0) {
            size_t gb = (size_t)bn * NB;
            if (c0)
                atomicAdd(&g_hist[gb + 0],
                    ((u64)(c0 >> 16) << 47) | ((u64)(c0 & 0xFFFFu) << 30) | (u64)s0);
            if (cM)
                atomicAdd(&g_hist[gb + NB - 1],
                    ((u64)(cM >> 16) << 47) | ((u64)(cM & 0xFFFFu) << 30) | (u64)sM);
        }
        __syncthreads();
        // merge smem mid-bins into global (batched, outside hot loop)
        size_t gb0 = (size_t)b * Nq * NB;
        for (int k = tid; k < Nq * NB; k += THREADS) {
            u64 h = shist[k];
            if (h) atomicAdd(&g_hist[gb0 + k], h);
        }
    }

    gridbar(3);

    // ================= phase 4: Lovász scan (blocks 0..23) ================
    if (blk >= BN) return;
    {
        int ibn = blk;
        float gts = g_cnt[ibn];
        size_t gbase = (size_t)ibn * NB;

        u32 pos = 0, tot = 0, fxv = 0;
        u64 tsum = 0ull;
        if (tid < LTH) {
            int bin = NB - 1 - tid;     // descending position
            u64 h = g_hist[gbase + bin];
            pos = (u32)(h >> 47);
            u32 neg = (u32)(h >> 30) & 0x1FFFFu;
            tot = pos + neg;
            fxv = (u32)(h & 0x3FFFFFFFull);
            tsum = ((u64)pos << 32) | (u64)tot;
        }

        // hand-rolled exclusive scan over 256 lanes (8 warps)
        __shared__ u64 wtot[8];
        u64 inc = tsum;
        if (tid < LTH) {
#pragma unroll
            for (int off = 1; off < 32; off <<= 1) {
                u64 n = __shfl_up_sync(0xFFFFFFFFu, inc, off);
                if (lane >= off) inc += n;
            }
            if (lane == 31) wtot[w] = inc;
        }
        __syncthreads();
        float loss = 0.f;
        if (tid < LTH && tot) {
            u64 wpref = 0ull;
            for (int ww = 0; ww < w; ww++) wpref += wtot[ww];
            u64 run = wpref + inc - tsum;    // exclusive prefix
            float cA = (float)(u32)(run >> 32);
            float kA = (float)(u32)(run & 0xFFFFFFFFull);
            float cB = cA + (float)pos;
            float kB = kA + (float)tot;
            float JA = 1.0f - (gts - cA) / (gts + kA - cA);
            float JB = 1.0f - (gts - cB) / (gts + kB - cB);
            float err_rep = (float)fxv / (FXS * (float)tot);
            loss = err_rep * (JB - JA);
        }

        __shared__ float red[LTH];
        if (tid < LTH) red[tid] = loss;
        __syncthreads();
        for (int s = LTH / 2; s > 0; s >>= 1) {
            if (tid < s) red[tid] += red[tid + s];
            __syncthreads();
        }

        __shared__ bool is_last;
        if (tid == 0) {
            g_losspart[ibn] = red[0];
            __threadfence();
            int done = atomicAdd(&g_done_l, 1);
            is_last = (done == BN - 1);
        }
        __syncthreads();
        if (is_last && tid == 0) {
            __threadfence();
            float s = 0.f;
#pragma unroll
            for (int i = 0; i < BN; i++) s += g_losspart[i];
            out[0] = s / (float)BN;
            g_done_l = 0;               // reset for next replay
        }
    }
}

extern "C" void kernel_launch(void* const* d_in, const int* in_sizes, int n_in,
                              void* d_out, int out_size) {
    const float* f1 = (const float*)d_in[0];
    const float* f2 = (const float*)d_in[1];
    const int*   gt = (const int*)d_in[2];
    float* out = (float*)d_out;
    cudaFuncSetAttribute(k_fused, cudaFuncAttributeMaxDynamicSharedMemorySize,
                         SMEM_DYN);
    k_fused<<<NBLK, THREADS, SMEM_DYN>>>(f1, f2, gt, out);
}